// round 11
// baseline (speedup 1.0000x reference)
#include <cuda_runtime.h>
#include <cuda_fp16.h>
#include <math.h>
#include <stdint.h>

// Problem constants
#define B_   2
#define S_   2048
#define H_   2048
#define NH_  16
#define HD_  128
#define MTOT (B_ * S_)          // 4096 rows for projection GEMMs

// ---------------------------------------------------------------------------
// Device scratch (half precision operands everywhere)
// ---------------------------------------------------------------------------
__device__ __half g_q[(size_t)B_ * NH_ * S_ * HD_];
__device__ __half g_k[(size_t)B_ * NH_ * S_ * HD_];
__device__ __half g_v[(size_t)B_ * NH_ * S_ * HD_];
__device__ __half g_attn[(size_t)B_ * S_ * H_];
__device__ __half g_xh[(size_t)MTOT * H_];         // fp16 x
__device__ __half g_wt[(size_t)4 * H_ * H_];       // W^T (K-major), fp16

// ---------------------------------------------------------------------------
// Helpers
// ---------------------------------------------------------------------------
__device__ __forceinline__ uint32_t smem_u32(const void* p) {
    return (uint32_t)__cvta_generic_to_shared(p);
}
__device__ __forceinline__ void cp16(void* s, const void* g) {
    asm volatile("cp.async.cg.shared.global [%0], [%1], 16;"
                 :: "r"(smem_u32(s)), "l"(g));
}
__device__ __forceinline__ void cp_commit() {
    asm volatile("cp.async.commit_group;");
}
template <int N>
__device__ __forceinline__ void cp_wait() {
    asm volatile("cp.async.wait_group %0;" :: "n"(N));
}

__device__ __forceinline__ void ldmx4(uint32_t (&r)[4], uint32_t a) {
    asm volatile("ldmatrix.sync.aligned.m8n8.x4.shared.b16 {%0,%1,%2,%3}, [%4];"
                 : "=r"(r[0]), "=r"(r[1]), "=r"(r[2]), "=r"(r[3]) : "r"(a));
}
__device__ __forceinline__ void ldmx4t(uint32_t (&r)[4], uint32_t a) {
    asm volatile("ldmatrix.sync.aligned.m8n8.x4.trans.shared.b16 {%0,%1,%2,%3}, [%4];"
                 : "=r"(r[0]), "=r"(r[1]), "=r"(r[2]), "=r"(r[3]) : "r"(a));
}

// m16n8k16 fp16 mma, fp32 accumulate.
__device__ __forceinline__ void mma_f16(float (&c)[4], const uint32_t (&a)[4],
                                        uint32_t b0, uint32_t b1) {
    asm volatile(
        "mma.sync.aligned.m16n8k16.row.col.f32.f16.f16.f32 "
        "{%0,%1,%2,%3}, {%4,%5,%6,%7}, {%8,%9}, {%0,%1,%2,%3};\n"
        : "+f"(c[0]), "+f"(c[1]), "+f"(c[2]), "+f"(c[3])
        : "r"(a[0]), "r"(a[1]), "r"(a[2]), "r"(a[3]), "r"(b0), "r"(b1));
}

__device__ __forceinline__ uint32_t packh2(float lo, float hi) {
    __half2 h = __float22half2_rn(make_float2(lo, hi));
    return *reinterpret_cast<uint32_t*>(&h);
}

// ---------------------------------------------------------------------------
// Prep: x -> fp16; all 4 weights -> W^T fp16 (K-major) in ONE launch
// ---------------------------------------------------------------------------
__global__ void halfcast(const float* __restrict__ src, __half* __restrict__ dst,
                         int n4)
{
    int i = blockIdx.x * blockDim.x + threadIdx.x;
    if (i < n4) {
        float4 v = ((const float4*)src)[i];
        uint2 o;
        o.x = packh2(v.x, v.y);
        o.y = packh2(v.z, v.w);
        ((uint2*)dst)[i] = o;
    }
}

__global__ void transpose_half4(const float* __restrict__ W0,
                                const float* __restrict__ W1,
                                const float* __restrict__ W2,
                                const float* __restrict__ W3,
                                __half* __restrict__ Wt)
{
    const int z = blockIdx.z;
    const float* W = (z == 0) ? W0 : (z == 1) ? W1 : (z == 2) ? W2 : W3;
    __half* dst = Wt + (size_t)z * H_ * H_;

    __shared__ float t[32][33];
    int n0 = blockIdx.x * 32, k0 = blockIdx.y * 32;
    int tx = threadIdx.x, ty = threadIdx.y;
    #pragma unroll
    for (int i = 0; i < 4; i++)
        t[ty + i * 8][tx] = W[(size_t)(k0 + ty + i * 8) * H_ + n0 + tx];
    __syncthreads();
    #pragma unroll
    for (int i = 0; i < 4; i++)
        dst[(size_t)(n0 + ty + i * 8) * H_ + k0 + tx] = __float2half(t[tx][ty + i * 8]);
}

// ---------------------------------------------------------------------------
// fp16 GEMM 128x128, warp tile 64x32, BK=64, 3-stage cp.async pipeline,
// NOW with explicit fragment double-buffering across k16 steps (ldmatrix of
// step k+1 issued before the mmas of step k -> LDSM latency hidden in-warp).
// Row stride 144 B (conflict-free ldmatrix phases). 2 CTAs/SM.
// ---------------------------------------------------------------------------
#define GH_ROWB 144
#define GH_STGB (256 * GH_ROWB)            // 36864 B per stage
#define GH_SMEM (3 * GH_STGB)              // 110592 B
#define GH_BK   64

template <bool FUSED>
__global__ __launch_bounds__(256, 2)
void gemm_h(const __half* __restrict__ A, const __half* __restrict__ Wt,
            const float* __restrict__ b0v, const float* __restrict__ b1v,
            const float* __restrict__ b2v,
            __half* __restrict__ o0, __half* __restrict__ o1,
            __half* __restrict__ o2, float* __restrict__ of)
{
    constexpr int K = H_;
    extern __shared__ char smc[];
    const uint32_t sbase = smem_u32(smc);

    const int tid = threadIdx.x;
    const int w = tid >> 5, lane = tid & 31, g = lane >> 2, t4 = lane & 3;
    const int wr = w >> 2, wc = w & 3;
    const int mBase = blockIdx.y * 128;
    const int nBase = blockIdx.x * 128;

    float acc[4][4][4] = {};

    auto loadStage = [&](int kt, int s) {
        char* St = smc + s * GH_STGB;
        const int k0 = kt * GH_BK;
        #pragma unroll
        for (int i = 0; i < 4; i++) {      // A: 1024 16B chunks
            int id = tid + i * 256;
            int r = id >> 3, c = id & 7;
            cp16(St + r * GH_ROWB + c * 16,
                 A + (size_t)(mBase + r) * K + k0 + c * 8);
        }
        #pragma unroll
        for (int i = 0; i < 4; i++) {      // B: 1024 16B chunks
            int id = tid + i * 256;
            int r = id >> 3, c = id & 7;
            cp16(St + (128 + r) * GH_ROWB + c * 16,
                 Wt + (size_t)(nBase + r) * K + k0 + c * 8);
        }
    };

    const int nIter = K / GH_BK;   // 32
    loadStage(0, 0); cp_commit();
    loadStage(1, 1); cp_commit();

    const int aRow = wr * 64 + (lane & 15);
    const int aChunk = (lane >> 4) << 4;
    const int li = lane >> 3;
    const int bRowOff = ((li >> 1) << 3) + (lane & 7);
    const int bChunk = (li & 1) << 4;

    // double-buffered fragment sets
    uint32_t af[2][4][4], bf[2][2][4];

    auto loadFrags = [&](uint32_t Ab, uint32_t Bb, int k16, int set) {
        #pragma unroll
        for (int mi = 0; mi < 4; mi++)
            ldmx4(af[set][mi], Ab + (aRow + mi * 16) * GH_ROWB + aChunk + k16 * 32);
        #pragma unroll
        for (int np = 0; np < 2; np++)
            ldmx4(bf[set][np], Bb + (wc * 32 + np * 16 + bRowOff) * GH_ROWB
                               + bChunk + k16 * 32);
    };
    auto doMMA = [&](int set) {
        #pragma unroll
        for (int mi = 0; mi < 4; mi++)
            #pragma unroll
            for (int np = 0; np < 2; np++) {
                mma_f16(acc[mi][np * 2 + 0], af[set][mi],
                        bf[set][np][0], bf[set][np][1]);
                mma_f16(acc[mi][np * 2 + 1], af[set][mi],
                        bf[set][np][2], bf[set][np][3]);
            }
    };

    for (int kt = 0; kt < nIter; kt++) {
        cp_wait<1>();
        __syncthreads();

        const int nt = kt + 2;
        if (nt < nIter) loadStage(nt, nt % 3);
        cp_commit();

        const uint32_t Ab = sbase + (kt % 3) * GH_STGB;
        const uint32_t Bb = Ab + 128 * GH_ROWB;

        loadFrags(Ab, Bb, 0, 0);
        #pragma unroll
        for (int k16 = 0; k16 < 4; k16++) {
            const int cur = k16 & 1;
            if (k16 < 3) loadFrags(Ab, Bb, k16 + 1, cur ^ 1);
            doMMA(cur);
        }
    }

    #pragma unroll
    for (int mi = 0; mi < 4; mi++) {
        #pragma unroll
        for (int r2 = 0; r2 < 2; r2++) {
            const int m = mBase + wr * 64 + mi * 16 + g + r2 * 8;
            #pragma unroll
            for (int ni = 0; ni < 4; ni++) {
                const int n = nBase + wc * 32 + ni * 8 + 2 * t4;
                if (FUSED) {
                    const int which = n >> 11;        // 0=Q 1=K 2=V
                    const int n2 = n & (H_ - 1);
                    const float* bias = (which == 0) ? b0v : (which == 1) ? b1v : b2v;
                    __half* dst = (which == 0) ? o0 : (which == 1) ? o1 : o2;
                    const int b = m >> 11;
                    const int s = m & (S_ - 1);
                    const int h = n2 >> 7;
                    const int d = n2 & (HD_ - 1);
                    uint32_t pv = packh2(acc[mi][ni][r2 * 2 + 0] + bias[n2],
                                         acc[mi][ni][r2 * 2 + 1] + bias[n2 + 1]);
                    *(uint32_t*)&dst[(((size_t)(b * NH_ + h)) * S_ + s) * HD_ + d] = pv;
                } else {
                    float2 v;
                    v.x = acc[mi][ni][r2 * 2 + 0] + b0v[n];
                    v.y = acc[mi][ni][r2 * 2 + 1] + b0v[n + 1];
                    *(float2*)&of[(size_t)m * H_ + n] = v;
                }
            }
        }
    }
}

// ---------------------------------------------------------------------------
// fp16 flash attention, BKT=64, double-buffered K/V (Round 9/10 — proven).
// Byte-identical to Round 10.
// ---------------------------------------------------------------------------
#define AT_BK   64
#define AQ_ROWB 272
#define AT_KVB  (AT_BK * AQ_ROWB)                              // 17408 B
#define AT_SMEM (128 * AQ_ROWB + 4 * AT_KVB + 2 * AT_BK * 4)   // 104960 B

__global__ __launch_bounds__(256, 2)
void attn_h(const __half* __restrict__ Q, const __half* __restrict__ K,
            const __half* __restrict__ V, const float* __restrict__ mask,
            __half* __restrict__ out)
{
    extern __shared__ char smc[];
    char* Qs = smc;                              // 128 x 272 B
    char* KV = Qs + 128 * AQ_ROWB;               // 2 x (K 64x272 + V 64x272)
    float* msk = (float*)(KV + 4 * AT_KVB);      // 2 x 64 floats
    const uint32_t qbase  = smem_u32(Qs);
    const uint32_t kvbase = smem_u32(KV);

    const int tid = threadIdx.x;
    const int w = tid >> 5, lane = tid & 31, g = lane >> 2, t4 = lane & 3;
    const int bh = blockIdx.y;
    const int b  = bh >> 4;
    const int q0 = blockIdx.x * 128;

    const __half* Qg = Q + ((size_t)bh * S_ + q0) * HD_;
    const __half* Kg = K + (size_t)bh * S_ * HD_;
    const __half* Vg = V + (size_t)bh * S_ * HD_;
    const float* maskg = mask + (size_t)b * S_;

    #pragma unroll
    for (int i = 0; i < 8; i++) {
        int id = tid + i * 256;
        int r = id >> 4, c = id & 15;
        cp16(Qs + r * AQ_ROWB + c * 16, Qg + (size_t)r * HD_ + c * 8);
    }
    auto loadKV = [&](int kb0, int buf) {
        char* Kb = KV + buf * 2 * AT_KVB;
        char* Vb = Kb + AT_KVB;
        #pragma unroll
        for (int i = 0; i < 4; i++) {
            int id = tid + i * 256;
            int r = id >> 4, c = id & 15;
            cp16(Kb + r * AQ_ROWB + c * 16, Kg + (size_t)(kb0 + r) * HD_ + c * 8);
            cp16(Vb + r * AQ_ROWB + c * 16, Vg + (size_t)(kb0 + r) * HD_ + c * 8);
        }
        if (tid < AT_BK) msk[buf * AT_BK + tid] = maskg[kb0 + tid];
    };
    loadKV(0, 0);       cp_commit();   // G0 (incl. Q)
    loadKV(AT_BK, 1);   cp_commit();   // G1

    float O[16][4];
    #pragma unroll
    for (int nt = 0; nt < 16; nt++)
        #pragma unroll
        for (int c = 0; c < 4; c++) O[nt][c] = 0.f;
    float m_lo = -1e30f, m_hi = -1e30f, l_lo = 0.f, l_hi = 0.f;

    const float scale = 0.08838834764831845f;   // 1/sqrt(128)
    const int nIter = S_ / AT_BK;               // 32

    const int aRow = (lane & 15);
    const int aChunk = (lane >> 4) << 4;
    const int li = lane >> 3;
    const int bRowOff = ((li >> 1) << 3) + (lane & 7);
    const int bChunk = (li & 1) << 4;
    const uint32_t qaddr0 = qbase + (w * 16 + aRow) * AQ_ROWB + aChunk;

    for (int kt = 0; kt < nIter; kt++) {
        cp_wait<1>();                  // buffer kt&1 loads complete
        __syncthreads();

        const int buf = kt & 1;
        const uint32_t kbase = kvbase + buf * 2 * AT_KVB;
        const uint32_t vbase = kbase + AT_KVB;
        const float* mk = msk + buf * AT_BK;

        // ---- S = Q @ K^T (16x64 per warp), 8 k16 steps ----
        float sacc[8][4] = {};
        #pragma unroll
        for (int k16 = 0; k16 < 8; k16++) {
            uint32_t af[4], bf[4][4];
            ldmx4(af, qaddr0 + k16 * 32);
            #pragma unroll
            for (int np = 0; np < 4; np++)
                ldmx4(bf[np], kbase + (np * 16 + bRowOff) * AQ_ROWB
                              + bChunk + k16 * 32);
            #pragma unroll
            for (int np = 0; np < 4; np++) {
                mma_f16(sacc[np * 2 + 0], af, bf[np][0], bf[np][1]);
                mma_f16(sacc[np * 2 + 1], af, bf[np][2], bf[np][3]);
            }
        }

        // ---- scale + mask ----
        #pragma unroll
        for (int ni = 0; ni < 8; ni++)
            #pragma unroll
            for (int c = 0; c < 4; c++) {
                const int col = ni * 8 + 2 * t4 + (c & 1);
                sacc[ni][c] = sacc[ni][c] * scale + mk[col];
            }

        // ---- in-warp softmax ----
        float rm_lo = -1e30f, rm_hi = -1e30f;
        #pragma unroll
        for (int ni = 0; ni < 8; ni++) {
            rm_lo = fmaxf(rm_lo, fmaxf(sacc[ni][0], sacc[ni][1]));
            rm_hi = fmaxf(rm_hi, fmaxf(sacc[ni][2], sacc[ni][3]));
        }
        rm_lo = fmaxf(rm_lo, __shfl_xor_sync(0xffffffffu, rm_lo, 1));
        rm_lo = fmaxf(rm_lo, __shfl_xor_sync(0xffffffffu, rm_lo, 2));
        rm_hi = fmaxf(rm_hi, __shfl_xor_sync(0xffffffffu, rm_hi, 1));
        rm_hi = fmaxf(rm_hi, __shfl_xor_sync(0xffffffffu, rm_hi, 2));

        const float mn_lo = fmaxf(m_lo, rm_lo);
        const float mn_hi = fmaxf(m_hi, rm_hi);
        const float al_lo = __expf(m_lo - mn_lo);
        const float al_hi = __expf(m_hi - mn_hi);
        m_lo = mn_lo;
        m_hi = mn_hi;

        float sum_lo = 0.f, sum_hi = 0.f;
        #pragma unroll
        for (int ni = 0; ni < 8; ni++) {
            sacc[ni][0] = __expf(sacc[ni][0] - mn_lo);
            sacc[ni][1] = __expf(sacc[ni][1] - mn_lo);
            sacc[ni][2] = __expf(sacc[ni][2] - mn_hi);
            sacc[ni][3] = __expf(sacc[ni][3] - mn_hi);
            sum_lo += sacc[ni][0] + sacc[ni][1];
            sum_hi += sacc[ni][2] + sacc[ni][3];
        }
        sum_lo += __shfl_xor_sync(0xffffffffu, sum_lo, 1);
        sum_lo += __shfl_xor_sync(0xffffffffu, sum_lo, 2);
        sum_hi += __shfl_xor_sync(0xffffffffu, sum_hi, 1);
        sum_hi += __shfl_xor_sync(0xffffffffu, sum_hi, 2);
        l_lo = l_lo * al_lo + sum_lo;
        l_hi = l_hi * al_hi + sum_hi;

        #pragma unroll
        for (int nt = 0; nt < 16; nt++) {
            O[nt][0] *= al_lo;  O[nt][1] *= al_lo;
            O[nt][2] *= al_hi;  O[nt][3] *= al_hi;
        }

        // ---- O += P @ V ----
        #pragma unroll
        for (int kb = 0; kb < 4; kb++) {
            uint32_t af[4];
            af[0] = packh2(sacc[2 * kb][0],     sacc[2 * kb][1]);
            af[1] = packh2(sacc[2 * kb][2],     sacc[2 * kb][3]);
            af[2] = packh2(sacc[2 * kb + 1][0], sacc[2 * kb + 1][1]);
            af[3] = packh2(sacc[2 * kb + 1][2], sacc[2 * kb + 1][3]);
            #pragma unroll
            for (int t = 0; t < 8; t++) {
                uint32_t bf[4];
                ldmx4t(bf, vbase + (kb * 16 + aRow) * AQ_ROWB
                           + (2 * t) * 16 + aChunk);
                mma_f16(O[2 * t + 0], af, bf[0], bf[1]);
                mma_f16(O[2 * t + 1], af, bf[2], bf[3]);
            }
        }

        __syncthreads();               // all warps done with buf before refill
        const int nt2 = kt + 2;
        if (nt2 < nIter) loadKV(nt2 * AT_BK, buf);
        cp_commit();                   // unconditional (group accounting)
    }

    // ---- finalize ----
    const int h = bh & (NH_ - 1);
    const float inv_lo = 1.f / l_lo;
    const float inv_hi = 1.f / l_hi;
    const int q_lo = q0 + w * 16 + g;
    __half* dst_lo = out + ((size_t)b * S_ + q_lo) * H_ + h * HD_;
    __half* dst_hi = dst_lo + (size_t)8 * H_;
    #pragma unroll
    for (int nt = 0; nt < 16; nt++) {
        const int col = nt * 8 + 2 * t4;
        *(uint32_t*)&dst_lo[col] = packh2(O[nt][0] * inv_lo, O[nt][1] * inv_lo);
        *(uint32_t*)&dst_hi[col] = packh2(O[nt][2] * inv_hi, O[nt][3] * inv_hi);
    }
}

// ---------------------------------------------------------------------------
// Launch
// ---------------------------------------------------------------------------
extern "C" void kernel_launch(void* const* d_in, const int* in_sizes, int n_in,
                              void* d_out, int out_size)
{
    const float* x    = (const float*)d_in[0];
    const float* mask = (const float*)d_in[1];
    const float* Wq   = (const float*)d_in[2];
    const float* bq   = (const float*)d_in[3];
    const float* Wk   = (const float*)d_in[4];
    const float* bk   = (const float*)d_in[5];
    const float* Wv   = (const float*)d_in[6];
    const float* bv   = (const float*)d_in[7];
    const float* Wo   = (const float*)d_in[8];
    const float* bo   = (const float*)d_in[9];
    float* out = (float*)d_out;

    __half *q, *k, *v, *attn, *xh, *wt;
    cudaGetSymbolAddress((void**)&q,    g_q);
    cudaGetSymbolAddress((void**)&k,    g_k);
    cudaGetSymbolAddress((void**)&v,    g_v);
    cudaGetSymbolAddress((void**)&attn, g_attn);
    cudaGetSymbolAddress((void**)&xh,   g_xh);
    cudaGetSymbolAddress((void**)&wt,   g_wt);

    cudaFuncSetAttribute(gemm_h<true>,
                         cudaFuncAttributeMaxDynamicSharedMemorySize, GH_SMEM);
    cudaFuncSetAttribute(gemm_h<false>,
                         cudaFuncAttributeMaxDynamicSharedMemorySize, GH_SMEM);
    cudaFuncSetAttribute(attn_h,
                         cudaFuncAttributeMaxDynamicSharedMemorySize, AT_SMEM);

    // Prep: x -> fp16; all 4 weights transposed in one launch
    const int nx4 = MTOT * H_ / 4;
    halfcast<<<(nx4 + 255) / 256, 256>>>(x, xh, nx4);
    transpose_half4<<<dim3(H_ / 32, H_ / 32, 4), dim3(32, 8)>>>(Wq, Wk, Wv, Wo, wt);

    const size_t wsz = (size_t)H_ * H_;

    // Fused QKV projection (N = 3*2048, 128x128 tiles, BK=64)
    gemm_h<true><<<dim3(3 * H_ / 128, MTOT / 128), 256, GH_SMEM>>>(
        xh, wt, bq, bk, bv, q, k, v, nullptr);

    attn_h<<<dim3(S_ / 128, B_ * NH_), 256, AT_SMEM>>>(q, k, v, mask, attn);

    // Out projection (fp32 output)
    gemm_h<false><<<dim3(H_ / 128, MTOT / 128), 256, GH_SMEM>>>(
        attn, wt + 3 * wsz, bo, nullptr, nullptr,
        nullptr, nullptr, nullptr, out);
}

// round 12
// speedup vs baseline: 1.1053x; 1.1053x over previous
#include <cuda_runtime.h>
#include <cuda_fp16.h>
#include <math.h>
#include <stdint.h>

// Problem constants
#define B_   2
#define S_   2048
#define H_   2048
#define NH_  16
#define HD_  128
#define MTOT (B_ * S_)          // 4096 rows for projection GEMMs

// Blocked-stage geometry (one GEMM pipeline stage operand block)
#define ROWB   144              // bytes per row (16B pad -> conflict-free ldmatrix)
#define ROWH   72               // halves per row
#define BLKB   (128 * ROWB)     // 18432 B per operand block (128 rows x 64 halves)
#define BLKH   (128 * ROWH)     // 9216 halves

// ---------------------------------------------------------------------------
// Device scratch
// ---------------------------------------------------------------------------
__device__ __half g_q[(size_t)B_ * NH_ * S_ * HD_];
__device__ __half g_k[(size_t)B_ * NH_ * S_ * HD_];
__device__ __half g_v[(size_t)B_ * NH_ * S_ * HD_];
__device__ __half g_wt[(size_t)4 * H_ * H_];             // W^T (K-major) flat, fp16
__device__ __half g_xblk[(size_t)32 * 32 * BLKH];        // x, tile-blocked
__device__ __half g_wblk[(size_t)48 * 32 * BLKH];        // Wq|Wk|Wv^T, tile-blocked
__device__ __half g_wblk_o[(size_t)16 * 32 * BLKH];      // Wo^T, tile-blocked
__device__ __half g_ablk[(size_t)32 * 32 * BLKH];        // attn out, tile-blocked

// ---------------------------------------------------------------------------
// Helpers
// ---------------------------------------------------------------------------
__device__ __forceinline__ uint32_t smem_u32(const void* p) {
    return (uint32_t)__cvta_generic_to_shared(p);
}
__device__ __forceinline__ void cp16(void* s, const void* g) {
    asm volatile("cp.async.cg.shared.global [%0], [%1], 16;"
                 :: "r"(smem_u32(s)), "l"(g));
}
__device__ __forceinline__ void cp_commit() {
    asm volatile("cp.async.commit_group;");
}
template <int N>
__device__ __forceinline__ void cp_wait() {
    asm volatile("cp.async.wait_group %0;" :: "n"(N));
}

// TMA bulk copy global -> shared with mbarrier completion (sm_90 ISA)
__device__ __forceinline__ void tma_bulk(uint32_t dst, const void* src,
                                         uint32_t bytes, uint32_t mbar) {
    asm volatile(
        "cp.async.bulk.shared::cluster.global.mbarrier::complete_tx::bytes "
        "[%0], [%1], %2, [%3];"
        :: "r"(dst), "l"(src), "r"(bytes), "r"(mbar) : "memory");
}

#define MBAR_INIT(mbar, cnt) \
    asm volatile("mbarrier.init.shared.b64 [%0], %1;" :: "r"(mbar), "r"(cnt) : "memory")
#define MBAR_EXPECT_TX(mbar, bytes) \
    asm volatile("mbarrier.arrive.expect_tx.shared.b64 _, [%0], %1;" \
                 :: "r"(mbar), "r"(bytes) : "memory")
#define MBAR_WAIT(mbar, parity) do {                                        \
    uint32_t _m = (mbar), _p = (parity), _d;                                \
    asm volatile("{\n\t.reg .pred p;\n\t"                                   \
        "mbarrier.try_wait.parity.acquire.cta.shared::cta.b64 p, [%1], %2;\n\t" \
        "selp.b32 %0, 1, 0, p;\n\t}"                                        \
        : "=r"(_d) : "r"(_m), "r"(_p) : "memory");                          \
    if (!_d) {                                                              \
        asm volatile("{\n\t.reg .pred P1;\n\t"                              \
        "W_%=:\n\t"                                                         \
        "mbarrier.try_wait.parity.acquire.cta.shared::cta.b64 P1, [%0], %1, 0x989680;\n\t" \
        "@P1 bra.uni D_%=;\n\t"                                             \
        "bra.uni W_%=;\n\t"                                                 \
        "D_%=:\n\t}" :: "r"(_m), "r"(_p) : "memory");                       \
    }                                                                       \
} while (0)

__device__ __forceinline__ void ldmx4(uint32_t (&r)[4], uint32_t a) {
    asm volatile("ldmatrix.sync.aligned.m8n8.x4.shared.b16 {%0,%1,%2,%3}, [%4];"
                 : "=r"(r[0]), "=r"(r[1]), "=r"(r[2]), "=r"(r[3]) : "r"(a));
}
__device__ __forceinline__ void ldmx4t(uint32_t (&r)[4], uint32_t a) {
    asm volatile("ldmatrix.sync.aligned.m8n8.x4.trans.shared.b16 {%0,%1,%2,%3}, [%4];"
                 : "=r"(r[0]), "=r"(r[1]), "=r"(r[2]), "=r"(r[3]) : "r"(a));
}

// m16n8k16 fp16 mma, fp32 accumulate.
__device__ __forceinline__ void mma_f16(float (&c)[4], const uint32_t (&a)[4],
                                        uint32_t b0, uint32_t b1) {
    asm volatile(
        "mma.sync.aligned.m16n8k16.row.col.f32.f16.f16.f32 "
        "{%0,%1,%2,%3}, {%4,%5,%6,%7}, {%8,%9}, {%0,%1,%2,%3};\n"
        : "+f"(c[0]), "+f"(c[1]), "+f"(c[2]), "+f"(c[3])
        : "r"(a[0]), "r"(a[1]), "r"(a[2]), "r"(a[3]), "r"(b0), "r"(b1));
}

__device__ __forceinline__ uint32_t packh2(float lo, float hi) {
    __half2 h = __float22half2_rn(make_float2(lo, hi));
    return *reinterpret_cast<uint32_t*>(&h);
}

// ---------------------------------------------------------------------------
// Prep kernels
// ---------------------------------------------------------------------------
// x (fp32 [M][K]) -> fp16 tile-blocked (blk = (m>>7)*32 + (k>>6))
__global__ void x_to_blk(const float* __restrict__ x, __half* __restrict__ dst)
{
    int id = blockIdx.x * 256 + threadIdx.x;     // 32*32*1024 ids
    int blk = id >> 10;
    int r = (id >> 3) & 127;
    int c = id & 7;
    int m = (blk >> 5) * 128 + r;
    int k = (blk & 31) * 64 + c * 8;
    const float4* s = (const float4*)(x + (size_t)m * H_ + k);
    float4 v0 = s[0], v1 = s[1];
    uint4 o;
    o.x = packh2(v0.x, v0.y); o.y = packh2(v0.z, v0.w);
    o.z = packh2(v1.x, v1.y); o.w = packh2(v1.z, v1.w);
    *(uint4*)(dst + (size_t)blk * BLKH + r * ROWH + c * 8) = o;
}

// All 4 weights transposed to K-major flat fp16 in one launch
__global__ void transpose_half4(const float* __restrict__ W0,
                                const float* __restrict__ W1,
                                const float* __restrict__ W2,
                                const float* __restrict__ W3,
                                __half* __restrict__ Wt)
{
    const int z = blockIdx.z;
    const float* W = (z == 0) ? W0 : (z == 1) ? W1 : (z == 2) ? W2 : W3;
    __half* dst = Wt + (size_t)z * H_ * H_;

    __shared__ float t[32][33];
    int n0 = blockIdx.x * 32, k0 = blockIdx.y * 32;
    int tx = threadIdx.x, ty = threadIdx.y;
    #pragma unroll
    for (int i = 0; i < 4; i++)
        t[ty + i * 8][tx] = W[(size_t)(k0 + ty + i * 8) * H_ + n0 + tx];
    __syncthreads();
    #pragma unroll
    for (int i = 0; i < 4; i++)
        dst[(size_t)(n0 + ty + i * 8) * H_ + k0 + tx] = __float2half(t[tx][ty + i * 8]);
}

// K-major flat fp16 rows -> tile-blocked (nRows/128 * 32 blocks)
__global__ void w_to_blk(const __half* __restrict__ src, __half* __restrict__ dst)
{
    int id = blockIdx.x * 256 + threadIdx.x;
    int blk = id >> 10;
    int r = (id >> 3) & 127;
    int c = id & 7;
    int n = (blk >> 5) * 128 + r;
    int k = (blk & 31) * 64 + c * 8;
    uint4 v = *(const uint4*)(src + (size_t)n * H_ + k);
    *(uint4*)(dst + (size_t)blk * BLKH + r * ROWH + c * 8) = v;
}

// ---------------------------------------------------------------------------
// TMA-bulk fp16 GEMM: 128x128 CTA tile, warp tile 64x32, BK=64, 3-stage
// pipeline. Fills = 2 bulk copies per stage issued by ONE thread (no
// per-thread cp.async wavefronts). 2 CTAs/SM.
// FUSED: N spans stacked Q,K,V; epilogue scatters fp16 to [B][NH][S][HD].
// ---------------------------------------------------------------------------
#define GT_STGB (2 * BLKB)                 // 36864 B per stage (A + B)
#define GT_SMEM (3 * GT_STGB + 64)         // + mbarrier block

template <bool FUSED>
__global__ __launch_bounds__(256, 2)
void gemm_tma(const __half* __restrict__ Ablk, const __half* __restrict__ Bblk,
              const float* __restrict__ b0v, const float* __restrict__ b1v,
              const float* __restrict__ b2v,
              __half* __restrict__ o0, __half* __restrict__ o1,
              __half* __restrict__ o2, float* __restrict__ of)
{
    extern __shared__ char smc[];
    const uint32_t sbase = smem_u32(smc);
    const uint32_t mbase = sbase + 3 * GT_STGB;

    const int tid = threadIdx.x;
    const int w = tid >> 5, lane = tid & 31, g = lane >> 2, t4 = lane & 3;
    const int wr = w >> 2, wc = w & 3;
    const int mBlk = blockIdx.y;           // 128-row block of A
    const int nBlk = blockIdx.x;           // 128-row block of W^T

    if (tid == 0) {
        #pragma unroll
        for (int s = 0; s < 3; s++) MBAR_INIT(mbase + 8 * s, 1);
    }
    __syncthreads();

    const char* Ab8 = (const char*)Ablk;
    const char* Bb8 = (const char*)Bblk;
    auto issue = [&](int kt, int s) {
        if (tid == 0) {
            const uint32_t mb = mbase + 8 * s;
            MBAR_EXPECT_TX(mb, GT_STGB);
            tma_bulk(sbase + s * GT_STGB,
                     Ab8 + (size_t)(mBlk * 32 + kt) * BLKB, BLKB, mb);
            tma_bulk(sbase + s * GT_STGB + BLKB,
                     Bb8 + (size_t)(nBlk * 32 + kt) * BLKB, BLKB, mb);
        }
    };

    issue(0, 0);
    issue(1, 1);

    float acc[4][4][4] = {};
    const int aRow = wr * 64 + (lane & 15);
    const int aChunk = (lane >> 4) << 4;
    const int li = lane >> 3;
    const int bRowOff = ((li >> 1) << 3) + (lane & 7);
    const int bChunk = (li & 1) << 4;

    int ph[3] = {0, 0, 0};
    const int nIter = 32;                  // K=2048 / 64

    for (int kt = 0; kt < nIter; kt++) {
        const int s = kt % 3;
        MBAR_WAIT(mbase + 8 * s, ph[s]);
        ph[s] ^= 1;
        __syncthreads();                   // all warps done with stage (kt+2)%3

        if (kt + 2 < nIter) issue(kt + 2, (kt + 2) % 3);

        const uint32_t Ab = sbase + s * GT_STGB;
        const uint32_t Bb = Ab + BLKB;

        #pragma unroll
        for (int k16 = 0; k16 < 4; k16++) {
            uint32_t af[4][4], bf[2][4];
            #pragma unroll
            for (int mi = 0; mi < 4; mi++)
                ldmx4(af[mi], Ab + (aRow + mi * 16) * ROWB + aChunk + k16 * 32);
            #pragma unroll
            for (int np = 0; np < 2; np++)
                ldmx4(bf[np], Bb + (wc * 32 + np * 16 + bRowOff) * ROWB
                              + bChunk + k16 * 32);
            #pragma unroll
            for (int mi = 0; mi < 4; mi++)
                #pragma unroll
                for (int np = 0; np < 2; np++) {
                    mma_f16(acc[mi][np * 2 + 0], af[mi], bf[np][0], bf[np][1]);
                    mma_f16(acc[mi][np * 2 + 1], af[mi], bf[np][2], bf[np][3]);
                }
        }
    }

    const int mBase = mBlk * 128;
    const int nBase = nBlk * 128;
    #pragma unroll
    for (int mi = 0; mi < 4; mi++) {
        #pragma unroll
        for (int r2 = 0; r2 < 2; r2++) {
            const int m = mBase + wr * 64 + mi * 16 + g + r2 * 8;
            #pragma unroll
            for (int ni = 0; ni < 4; ni++) {
                const int n = nBase + wc * 32 + ni * 8 + 2 * t4;
                if (FUSED) {
                    const int which = n >> 11;        // 0=Q 1=K 2=V
                    const int n2 = n & (H_ - 1);
                    const float* bias = (which == 0) ? b0v : (which == 1) ? b1v : b2v;
                    __half* dst = (which == 0) ? o0 : (which == 1) ? o1 : o2;
                    const int b = m >> 11;
                    const int s = m & (S_ - 1);
                    const int h = n2 >> 7;
                    const int d = n2 & (HD_ - 1);
                    uint32_t pv = packh2(acc[mi][ni][r2 * 2 + 0] + bias[n2],
                                         acc[mi][ni][r2 * 2 + 1] + bias[n2 + 1]);
                    *(uint32_t*)&dst[(((size_t)(b * NH_ + h)) * S_ + s) * HD_ + d] = pv;
                } else {
                    float2 v;
                    v.x = acc[mi][ni][r2 * 2 + 0] + b0v[n];
                    v.y = acc[mi][ni][r2 * 2 + 1] + b0v[n + 1];
                    *(float2*)&of[(size_t)m * H_ + n] = v;
                }
            }
        }
    }
}

// ---------------------------------------------------------------------------
// fp16 flash attention, BKT=64, double-buffered K/V (proven R10 mainloop).
// Epilogue now writes the tile-blocked layout for the TMA out-projection.
// ---------------------------------------------------------------------------
#define AT_BK   64
#define AQ_ROWB 272
#define AT_KVB  (AT_BK * AQ_ROWB)                              // 17408 B
#define AT_SMEM (128 * AQ_ROWB + 4 * AT_KVB + 2 * AT_BK * 4)   // 104960 B

__global__ __launch_bounds__(256, 2)
void attn_h(const __half* __restrict__ Q, const __half* __restrict__ K,
            const __half* __restrict__ V, const float* __restrict__ mask,
            __half* __restrict__ ablk)
{
    extern __shared__ char smc[];
    char* Qs = smc;                              // 128 x 272 B
    char* KV = Qs + 128 * AQ_ROWB;               // 2 x (K 64x272 + V 64x272)
    float* msk = (float*)(KV + 4 * AT_KVB);      // 2 x 64 floats
    const uint32_t qbase  = smem_u32(Qs);
    const uint32_t kvbase = smem_u32(KV);

    const int tid = threadIdx.x;
    const int w = tid >> 5, lane = tid & 31, g = lane >> 2, t4 = lane & 3;
    const int bh = blockIdx.y;
    const int b  = bh >> 4;
    const int q0 = blockIdx.x * 128;

    const __half* Qg = Q + ((size_t)bh * S_ + q0) * HD_;
    const __half* Kg = K + (size_t)bh * S_ * HD_;
    const __half* Vg = V + (size_t)bh * S_ * HD_;
    const float* maskg = mask + (size_t)b * S_;

    #pragma unroll
    for (int i = 0; i < 8; i++) {
        int id = tid + i * 256;
        int r = id >> 4, c = id & 15;
        cp16(Qs + r * AQ_ROWB + c * 16, Qg + (size_t)r * HD_ + c * 8);
    }
    auto loadKV = [&](int kb0, int buf) {
        char* Kb = KV + buf * 2 * AT_KVB;
        char* Vb = Kb + AT_KVB;
        #pragma unroll
        for (int i = 0; i < 4; i++) {
            int id = tid + i * 256;
            int r = id >> 4, c = id & 15;
            cp16(Kb + r * AQ_ROWB + c * 16, Kg + (size_t)(kb0 + r) * HD_ + c * 8);
            cp16(Vb + r * AQ_ROWB + c * 16, Vg + (size_t)(kb0 + r) * HD_ + c * 8);
        }
        if (tid < AT_BK) msk[buf * AT_BK + tid] = maskg[kb0 + tid];
    };
    loadKV(0, 0);       cp_commit();   // G0 (incl. Q)
    loadKV(AT_BK, 1);   cp_commit();   // G1

    float O[16][4];
    #pragma unroll
    for (int nt = 0; nt < 16; nt++)
        #pragma unroll
        for (int c = 0; c < 4; c++) O[nt][c] = 0.f;
    float m_lo = -1e30f, m_hi = -1e30f, l_lo = 0.f, l_hi = 0.f;

    const float scale = 0.08838834764831845f;   // 1/sqrt(128)
    const int nIter = S_ / AT_BK;               // 32

    const int aRow = (lane & 15);
    const int aChunk = (lane >> 4) << 4;
    const int li = lane >> 3;
    const int bRowOff = ((li >> 1) << 3) + (lane & 7);
    const int bChunk = (li & 1) << 4;
    const uint32_t qaddr0 = qbase + (w * 16 + aRow) * AQ_ROWB + aChunk;

    for (int kt = 0; kt < nIter; kt++) {
        cp_wait<1>();                  // buffer kt&1 loads complete
        __syncthreads();

        const int buf = kt & 1;
        const uint32_t kbase = kvbase + buf * 2 * AT_KVB;
        const uint32_t vbase = kbase + AT_KVB;
        const float* mk = msk + buf * AT_BK;

        // ---- S = Q @ K^T (16x64 per warp), 8 k16 steps ----
        float sacc[8][4] = {};
        #pragma unroll
        for (int k16 = 0; k16 < 8; k16++) {
            uint32_t af[4], bf[4][4];
            ldmx4(af, qaddr0 + k16 * 32);
            #pragma unroll
            for (int np = 0; np < 4; np++)
                ldmx4(bf[np], kbase + (np * 16 + bRowOff) * AQ_ROWB
                              + bChunk + k16 * 32);
            #pragma unroll
            for (int np = 0; np < 4; np++) {
                mma_f16(sacc[np * 2 + 0], af, bf[np][0], bf[np][1]);
                mma_f16(sacc[np * 2 + 1], af, bf[np][2], bf[np][3]);
            }
        }

        // ---- scale + mask ----
        #pragma unroll
        for (int ni = 0; ni < 8; ni++)
            #pragma unroll
            for (int c = 0; c < 4; c++) {
                const int col = ni * 8 + 2 * t4 + (c & 1);
                sacc[ni][c] = sacc[ni][c] * scale + mk[col];
            }

        // ---- in-warp softmax ----
        float rm_lo = -1e30f, rm_hi = -1e30f;
        #pragma unroll
        for (int ni = 0; ni < 8; ni++) {
            rm_lo = fmaxf(rm_lo, fmaxf(sacc[ni][0], sacc[ni][1]));
            rm_hi = fmaxf(rm_hi, fmaxf(sacc[ni][2], sacc[ni][3]));
        }
        rm_lo = fmaxf(rm_lo, __shfl_xor_sync(0xffffffffu, rm_lo, 1));
        rm_lo = fmaxf(rm_lo, __shfl_xor_sync(0xffffffffu, rm_lo, 2));
        rm_hi = fmaxf(rm_hi, __shfl_xor_sync(0xffffffffu, rm_hi, 1));
        rm_hi = fmaxf(rm_hi, __shfl_xor_sync(0xffffffffu, rm_hi, 2));

        const float mn_lo = fmaxf(m_lo, rm_lo);
        const float mn_hi = fmaxf(m_hi, rm_hi);
        const float al_lo = __expf(m_lo - mn_lo);
        const float al_hi = __expf(m_hi - mn_hi);
        m_lo = mn_lo;
        m_hi = mn_hi;

        float sum_lo = 0.f, sum_hi = 0.f;
        #pragma unroll
        for (int ni = 0; ni < 8; ni++) {
            sacc[ni][0] = __expf(sacc[ni][0] - mn_lo);
            sacc[ni][1] = __expf(sacc[ni][1] - mn_lo);
            sacc[ni][2] = __expf(sacc[ni][2] - mn_hi);
            sacc[ni][3] = __expf(sacc[ni][3] - mn_hi);
            sum_lo += sacc[ni][0] + sacc[ni][1];
            sum_hi += sacc[ni][2] + sacc[ni][3];
        }
        sum_lo += __shfl_xor_sync(0xffffffffu, sum_lo, 1);
        sum_lo += __shfl_xor_sync(0xffffffffu, sum_lo, 2);
        sum_hi += __shfl_xor_sync(0xffffffffu, sum_hi, 1);
        sum_hi += __shfl_xor_sync(0xffffffffu, sum_hi, 2);
        l_lo = l_lo * al_lo + sum_lo;
        l_hi = l_hi * al_hi + sum_hi;

        #pragma unroll
        for (int nt = 0; nt < 16; nt++) {
            O[nt][0] *= al_lo;  O[nt][1] *= al_lo;
            O[nt][2] *= al_hi;  O[nt][3] *= al_hi;
        }

        // ---- O += P @ V ----
        #pragma unroll
        for (int kb = 0; kb < 4; kb++) {
            uint32_t af[4];
            af[0] = packh2(sacc[2 * kb][0],     sacc[2 * kb][1]);
            af[1] = packh2(sacc[2 * kb][2],     sacc[2 * kb][3]);
            af[2] = packh2(sacc[2 * kb + 1][0], sacc[2 * kb + 1][1]);
            af[3] = packh2(sacc[2 * kb + 1][2], sacc[2 * kb + 1][3]);
            #pragma unroll
            for (int t = 0; t < 8; t++) {
                uint32_t bf[4];
                ldmx4t(bf, vbase + (kb * 16 + aRow) * AQ_ROWB
                           + (2 * t) * 16 + aChunk);
                mma_f16(O[2 * t + 0], af, bf[0], bf[1]);
                mma_f16(O[2 * t + 1], af, bf[2], bf[3]);
            }
        }

        __syncthreads();               // all warps done with buf before refill
        const int nt2 = kt + 2;
        if (nt2 < nIter) loadKV(nt2 * AT_BK, buf);
        cp_commit();                   // unconditional (group accounting)
    }

    // ---- finalize: /l, fp16, write TILE-BLOCKED layout for out-proj ----
    const int h = bh & (NH_ - 1);
    const float inv_lo = 1.f / l_lo;
    const float inv_hi = 1.f / l_hi;
    const int q_lo = q0 + w * 16 + g;
    const int mlo = b * S_ + q_lo;               // global row in [MTOT]
    const int mBlkBase = (mlo >> 7) * 32;        // same block for lo & hi rows
    const int rlo = mlo & 127;
    #pragma unroll
    for (int nt = 0; nt < 16; nt++) {
        const int col = nt * 8 + 2 * t4;
        const int hcol = h * HD_ + col;
        const size_t base = ((size_t)(mBlkBase + (hcol >> 6))) * BLKH + (hcol & 63);
        *(uint32_t*)&ablk[base + rlo * ROWH] =
            packh2(O[nt][0] * inv_lo, O[nt][1] * inv_lo);
        *(uint32_t*)&ablk[base + (rlo + 8) * ROWH] =
            packh2(O[nt][2] * inv_hi, O[nt][3] * inv_hi);
    }
}

// ---------------------------------------------------------------------------
// Launch
// ---------------------------------------------------------------------------
extern "C" void kernel_launch(void* const* d_in, const int* in_sizes, int n_in,
                              void* d_out, int out_size)
{
    const float* x    = (const float*)d_in[0];
    const float* mask = (const float*)d_in[1];
    const float* Wq   = (const float*)d_in[2];
    const float* bq   = (const float*)d_in[3];
    const float* Wk   = (const float*)d_in[4];
    const float* bk   = (const float*)d_in[5];
    const float* Wv   = (const float*)d_in[6];
    const float* bv   = (const float*)d_in[7];
    const float* Wo   = (const float*)d_in[8];
    const float* bo   = (const float*)d_in[9];
    float* out = (float*)d_out;

    __half *q, *k, *v, *wt, *xblk, *wblk, *wblk_o, *ablk;
    cudaGetSymbolAddress((void**)&q,      g_q);
    cudaGetSymbolAddress((void**)&k,      g_k);
    cudaGetSymbolAddress((void**)&v,      g_v);
    cudaGetSymbolAddress((void**)&wt,     g_wt);
    cudaGetSymbolAddress((void**)&xblk,   g_xblk);
    cudaGetSymbolAddress((void**)&wblk,   g_wblk);
    cudaGetSymbolAddress((void**)&wblk_o, g_wblk_o);
    cudaGetSymbolAddress((void**)&ablk,   g_ablk);

    cudaFuncSetAttribute(gemm_tma<true>,
                         cudaFuncAttributeMaxDynamicSharedMemorySize, GT_SMEM);
    cudaFuncSetAttribute(gemm_tma<false>,
                         cudaFuncAttributeMaxDynamicSharedMemorySize, GT_SMEM);
    cudaFuncSetAttribute(attn_h,
                         cudaFuncAttributeMaxDynamicSharedMemorySize, AT_SMEM);

    const size_t wsz = (size_t)H_ * H_;

    // Prep: x -> blocked fp16; weights -> flat K-major fp16 -> blocked
    x_to_blk<<<4096, 256>>>(x, xblk);
    transpose_half4<<<dim3(H_ / 32, H_ / 32, 4), dim3(32, 8)>>>(Wq, Wk, Wv, Wo, wt);
    w_to_blk<<<6144, 256>>>(wt, wblk);               // Q|K|V (48 row-blocks)
    w_to_blk<<<2048, 256>>>(wt + 3 * wsz, wblk_o);   // O (16 row-blocks)

    // Fused QKV projection (N = 3*2048), TMA-bulk fills
    gemm_tma<true><<<dim3(48, 32), 256, GT_SMEM>>>(
        xblk, wblk, bq, bk, bv, q, k, v, nullptr);

    attn_h<<<dim3(S_ / 128, B_ * NH_), 256, AT_SMEM>>>(q, k, v, mask, ablk);

    // Out projection (fp32 output), TMA-bulk fills
    gemm_tma<false><<<dim3(16, 32), 256, GT_SMEM>>>(
        ablk, wblk_o, bo, nullptr, nullptr,
        nullptr, nullptr, nullptr, out);
}

// round 15
// speedup vs baseline: 1.1241x; 1.0171x over previous
#include <cuda_runtime.h>
#include <cuda_fp16.h>
#include <math.h>
#include <stdint.h>

// Problem constants
#define B_   2
#define S_   2048
#define H_   2048
#define NH_  16
#define HD_  128
#define MTOT (B_ * S_)          // 4096 rows for projection GEMMs

// Blocked-stage geometry (one GEMM pipeline stage operand block)
#define ROWB   144              // bytes per row (16B pad -> conflict-free ldmatrix)
#define ROWH   72               // halves per row
#define BLKB   (128 * ROWB)     // 18432 B per operand block (128 rows x 64 halves)
#define BLKH   (128 * ROWH)     // 9216 halves

// ---------------------------------------------------------------------------
// Device scratch
// ---------------------------------------------------------------------------
__device__ __half g_q[(size_t)B_ * NH_ * S_ * HD_];
__device__ __half g_k[(size_t)B_ * NH_ * S_ * HD_];
__device__ __half g_v[(size_t)B_ * NH_ * S_ * HD_];
__device__ __half g_xblk[(size_t)32 * 32 * BLKH];        // x, tile-blocked
__device__ __half g_wblk[(size_t)48 * 32 * BLKH];        // Wq|Wk|Wv^T, blocked
__device__ __half g_wblk_o[(size_t)16 * 32 * BLKH];      // Wo^T, blocked
__device__ __half g_ablk[(size_t)32 * 32 * BLKH];        // attn out, blocked

// ---------------------------------------------------------------------------
// Helpers
// ---------------------------------------------------------------------------
__device__ __forceinline__ uint32_t smem_u32(const void* p) {
    return (uint32_t)__cvta_generic_to_shared(p);
}
__device__ __forceinline__ void cp16(void* s, const void* g) {
    asm volatile("cp.async.cg.shared.global [%0], [%1], 16;"
                 :: "r"(smem_u32(s)), "l"(g));
}
__device__ __forceinline__ void cp_commit() {
    asm volatile("cp.async.commit_group;");
}
template <int N>
__device__ __forceinline__ void cp_wait() {
    asm volatile("cp.async.wait_group %0;" :: "n"(N));
}

// TMA bulk copy global -> shared with mbarrier completion (sm_90 ISA)
__device__ __forceinline__ void tma_bulk(uint32_t dst, const void* src,
                                         uint32_t bytes, uint32_t mbar) {
    asm volatile(
        "cp.async.bulk.shared::cluster.global.mbarrier::complete_tx::bytes "
        "[%0], [%1], %2, [%3];"
        :: "r"(dst), "l"(src), "r"(bytes), "r"(mbar) : "memory");
}

#define MBAR_INIT(mbar, cnt) \
    asm volatile("mbarrier.init.shared.b64 [%0], %1;" :: "r"(mbar), "r"(cnt) : "memory")
#define MBAR_EXPECT_TX(mbar, bytes) \
    asm volatile("mbarrier.arrive.expect_tx.shared.b64 _, [%0], %1;" \
                 :: "r"(mbar), "r"(bytes) : "memory")
#define MBAR_WAIT(mbar, parity) do {                                        \
    uint32_t _m = (mbar), _p = (parity), _d;                                \
    asm volatile("{\n\t.reg .pred p;\n\t"                                   \
        "mbarrier.try_wait.parity.acquire.cta.shared::cta.b64 p, [%1], %2;\n\t" \
        "selp.b32 %0, 1, 0, p;\n\t}"                                        \
        : "=r"(_d) : "r"(_m), "r"(_p) : "memory");                          \
    if (!_d) {                                                              \
        asm volatile("{\n\t.reg .pred P1;\n\t"                              \
        "W_%=:\n\t"                                                         \
        "mbarrier.try_wait.parity.acquire.cta.shared::cta.b64 P1, [%0], %1, 0x989680;\n\t" \
        "@P1 bra.uni D_%=;\n\t"                                             \
        "bra.uni W_%=;\n\t"                                                 \
        "D_%=:\n\t}" :: "r"(_m), "r"(_p) : "memory");                       \
    }                                                                       \
} while (0)

__device__ __forceinline__ void ldmx4(uint32_t (&r)[4], uint32_t a) {
    asm volatile("ldmatrix.sync.aligned.m8n8.x4.shared.b16 {%0,%1,%2,%3}, [%4];"
                 : "=r"(r[0]), "=r"(r[1]), "=r"(r[2]), "=r"(r[3]) : "r"(a));
}
__device__ __forceinline__ void ldmx4t(uint32_t (&r)[4], uint32_t a) {
    asm volatile("ldmatrix.sync.aligned.m8n8.x4.trans.shared.b16 {%0,%1,%2,%3}, [%4];"
                 : "=r"(r[0]), "=r"(r[1]), "=r"(r[2]), "=r"(r[3]) : "r"(a));
}

// m16n8k16 fp16 mma, fp32 accumulate.
__device__ __forceinline__ void mma_f16(float (&c)[4], const uint32_t (&a)[4],
                                        uint32_t b0, uint32_t b1) {
    asm volatile(
        "mma.sync.aligned.m16n8k16.row.col.f32.f16.f16.f32 "
        "{%0,%1,%2,%3}, {%4,%5,%6,%7}, {%8,%9}, {%0,%1,%2,%3};\n"
        : "+f"(c[0]), "+f"(c[1]), "+f"(c[2]), "+f"(c[3])
        : "r"(a[0]), "r"(a[1]), "r"(a[2]), "r"(a[3]), "r"(b0), "r"(b1));
}

__device__ __forceinline__ uint32_t packh2(float lo, float hi) {
    __half2 h = __float22half2_rn(make_float2(lo, hi));
    return *reinterpret_cast<uint32_t*>(&h);
}

// ---------------------------------------------------------------------------
// Prep kernels
// ---------------------------------------------------------------------------
// x (fp32 [M][K]) -> fp16 tile-blocked (blk = (m>>7)*32 + (k>>6))
__global__ void x_to_blk(const float* __restrict__ x, __half* __restrict__ dst)
{
    int id = blockIdx.x * 256 + threadIdx.x;     // 32*32*1024 ids
    int blk = id >> 10;
    int r = (id >> 3) & 127;
    int c = id & 7;
    int m = (blk >> 5) * 128 + r;
    int k = (blk & 31) * 64 + c * 8;
    const float4* s = (const float4*)(x + (size_t)m * H_ + k);
    float4 v0 = s[0], v1 = s[1];
    uint4 o;
    o.x = packh2(v0.x, v0.y); o.y = packh2(v0.z, v0.w);
    o.z = packh2(v1.x, v1.y); o.w = packh2(v1.z, v1.w);
    *(uint4*)(dst + (size_t)blk * BLKH + r * ROWH + c * 8) = o;
}

// Transpose + fp16 + tile-blocked directly (no flat intermediate)
__global__ void transpose_blk4(const float* __restrict__ W0,
                               const float* __restrict__ W1,
                               const float* __restrict__ W2,
                               const float* __restrict__ W3,
                               __half* __restrict__ wqkv,
                               __half* __restrict__ wo)
{
    const int z = blockIdx.z;
    const float* W = (z == 0) ? W0 : (z == 1) ? W1 : (z == 2) ? W2 : W3;

    __shared__ float t[32][33];
    int n0 = blockIdx.x * 32, k0 = blockIdx.y * 32;
    int tx = threadIdx.x, ty = threadIdx.y;
    #pragma unroll
    for (int i = 0; i < 4; i++)
        t[ty + i * 8][tx] = W[(size_t)(k0 + ty + i * 8) * H_ + n0 + tx];
    __syncthreads();
    __half* dst = (z < 3) ? wqkv : wo;
    const int nOff = (z < 3) ? z * H_ : 0;
    const int k = k0 + tx;
    #pragma unroll
    for (int i = 0; i < 4; i++) {
        const int nG = nOff + n0 + ty + i * 8;
        dst[((size_t)((nG >> 7) * 32 + (k >> 6))) * BLKH
            + (nG & 127) * ROWH + (k & 63)] = __float2half(t[tx][ty + i * 8]);
    }
}

// ---------------------------------------------------------------------------
// TMA-bulk fp16 GEMM (Round 12, PROVEN): 128x128 CTA tile, warp tile 64x32,
// BK=64, 3-stage pipeline, single-thread bulk fills, 2 CTAs/SM.
// FUSED: N spans stacked Q,K,V; epilogue scatters fp16 to [B][NH][S][HD].
// ---------------------------------------------------------------------------
#define GT_STGB (2 * BLKB)                 // 36864 B per stage (A + B)
#define GT_SMEM (3 * GT_STGB + 64)         // + mbarrier block

template <bool FUSED>
__global__ __launch_bounds__(256, 2)
void gemm_tma(const __half* __restrict__ Ablk, const __half* __restrict__ Bblk,
              const float* __restrict__ b0v, const float* __restrict__ b1v,
              const float* __restrict__ b2v,
              __half* __restrict__ o0, __half* __restrict__ o1,
              __half* __restrict__ o2, float* __restrict__ of)
{
    extern __shared__ char smc[];
    const uint32_t sbase = smem_u32(smc);
    const uint32_t mbase = sbase + 3 * GT_STGB;

    const int tid = threadIdx.x;
    const int w = tid >> 5, lane = tid & 31, g = lane >> 2, t4 = lane & 3;
    const int wr = w >> 2, wc = w & 3;
    const int mBlk = blockIdx.y;           // 128-row block of A
    const int nBlk = blockIdx.x;           // 128-row block of W^T

    if (tid == 0) {
        #pragma unroll
        for (int s = 0; s < 3; s++) MBAR_INIT(mbase + 8 * s, 1);
    }
    __syncthreads();

    const char* Ab8 = (const char*)Ablk;
    const char* Bb8 = (const char*)Bblk;
    auto issue = [&](int kt, int s) {
        if (tid == 0) {
            const uint32_t mb = mbase + 8 * s;
            MBAR_EXPECT_TX(mb, GT_STGB);
            tma_bulk(sbase + s * GT_STGB,
                     Ab8 + (size_t)(mBlk * 32 + kt) * BLKB, BLKB, mb);
            tma_bulk(sbase + s * GT_STGB + BLKB,
                     Bb8 + (size_t)(nBlk * 32 + kt) * BLKB, BLKB, mb);
        }
    };

    issue(0, 0);
    issue(1, 1);

    float acc[4][4][4] = {};
    const int aRow = wr * 64 + (lane & 15);
    const int aChunk = (lane >> 4) << 4;
    const int li = lane >> 3;
    const int bRowOff = ((li >> 1) << 3) + (lane & 7);
    const int bChunk = (li & 1) << 4;

    int ph[3] = {0, 0, 0};
    const int nIter = 32;                  // K=2048 / 64

    for (int kt = 0; kt < nIter; kt++) {
        const int s = kt % 3;
        MBAR_WAIT(mbase + 8 * s, ph[s]);
        ph[s] ^= 1;
        __syncthreads();                   // all warps done with stage (kt+2)%3

        if (kt + 2 < nIter) issue(kt + 2, (kt + 2) % 3);

        const uint32_t Ab = sbase + s * GT_STGB;
        const uint32_t Bb = Ab + BLKB;

        #pragma unroll
        for (int k16 = 0; k16 < 4; k16++) {
            uint32_t af[4][4], bf[2][4];
            #pragma unroll
            for (int mi = 0; mi < 4; mi++)
                ldmx4(af[mi], Ab + (aRow + mi * 16) * ROWB + aChunk + k16 * 32);
            #pragma unroll
            for (int np = 0; np < 2; np++)
                ldmx4(bf[np], Bb + (wc * 32 + np * 16 + bRowOff) * ROWB
                              + bChunk + k16 * 32);
            #pragma unroll
            for (int mi = 0; mi < 4; mi++)
                #pragma unroll
                for (int np = 0; np < 2; np++) {
                    mma_f16(acc[mi][np * 2 + 0], af[mi], bf[np][0], bf[np][1]);
                    mma_f16(acc[mi][np * 2 + 1], af[mi], bf[np][2], bf[np][3]);
                }
        }
    }

    const int mBase = mBlk * 128;
    const int nBase = nBlk * 128;
    #pragma unroll
    for (int mi = 0; mi < 4; mi++) {
        #pragma unroll
        for (int r2 = 0; r2 < 2; r2++) {
            const int m = mBase + wr * 64 + mi * 16 + g + r2 * 8;
            #pragma unroll
            for (int ni = 0; ni < 4; ni++) {
                const int n = nBase + wc * 32 + ni * 8 + 2 * t4;
                if (FUSED) {
                    const int which = n >> 11;        // 0=Q 1=K 2=V
                    const int n2 = n & (H_ - 1);
                    const float* bias = (which == 0) ? b0v : (which == 1) ? b1v : b2v;
                    __half* dst = (which == 0) ? o0 : (which == 1) ? o1 : o2;
                    const int b = m >> 11;
                    const int s = m & (S_ - 1);
                    const int h = n2 >> 7;
                    const int d = n2 & (HD_ - 1);
                    uint32_t pv = packh2(acc[mi][ni][r2 * 2 + 0] + bias[n2],
                                         acc[mi][ni][r2 * 2 + 1] + bias[n2 + 1]);
                    *(uint32_t*)&dst[(((size_t)(b * NH_ + h)) * S_ + s) * HD_ + d] = pv;
                } else {
                    float2 v;
                    v.x = acc[mi][ni][r2 * 2 + 0] + b0v[n];
                    v.y = acc[mi][ni][r2 * 2 + 1] + b0v[n + 1];
                    *(float2*)&of[(size_t)m * H_ + n] = v;
                }
            }
        }
    }
}

// ---------------------------------------------------------------------------
// fp16 flash attention, BKT=64, double-buffered K/V (Round 12, PROVEN —
// byte-identical mainloop). Epilogue writes tile-blocked attn for out-proj.
// ---------------------------------------------------------------------------
#define AT_BK   64
#define AQ_ROWB 272
#define AT_KVB  (AT_BK * AQ_ROWB)                              // 17408 B
#define AT_SMEM (128 * AQ_ROWB + 4 * AT_KVB + 2 * AT_BK * 4)   // 104960 B

__global__ __launch_bounds__(256, 2)
void attn_h(const __half* __restrict__ Q, const __half* __restrict__ K,
            const __half* __restrict__ V, const float* __restrict__ mask,
            __half* __restrict__ ablk)
{
    extern __shared__ char smc[];
    char* Qs = smc;                              // 128 x 272 B
    char* KV = Qs + 128 * AQ_ROWB;               // 2 x (K 64x272 + V 64x272)
    float* msk = (float*)(KV + 4 * AT_KVB);      // 2 x 64 floats
    const uint32_t qbase  = smem_u32(Qs);
    const uint32_t kvbase = smem_u32(KV);

    const int tid = threadIdx.x;
    const int w = tid >> 5, lane = tid & 31, g = lane >> 2, t4 = lane & 3;
    const int bh = blockIdx.y;
    const int b  = bh >> 4;
    const int q0 = blockIdx.x * 128;

    const __half* Qg = Q + ((size_t)bh * S_ + q0) * HD_;
    const __half* Kg = K + (size_t)bh * S_ * HD_;
    const __half* Vg = V + (size_t)bh * S_ * HD_;
    const float* maskg = mask + (size_t)b * S_;

    #pragma unroll
    for (int i = 0; i < 8; i++) {
        int id = tid + i * 256;
        int r = id >> 4, c = id & 15;
        cp16(Qs + r * AQ_ROWB + c * 16, Qg + (size_t)r * HD_ + c * 8);
    }
    auto loadKV = [&](int kb0, int buf) {
        char* Kb = KV + buf * 2 * AT_KVB;
        char* Vb = Kb + AT_KVB;
        #pragma unroll
        for (int i = 0; i < 4; i++) {
            int id = tid + i * 256;
            int r = id >> 4, c = id & 15;
            cp16(Kb + r * AQ_ROWB + c * 16, Kg + (size_t)(kb0 + r) * HD_ + c * 8);
            cp16(Vb + r * AQ_ROWB + c * 16, Vg + (size_t)(kb0 + r) * HD_ + c * 8);
        }
        if (tid < AT_BK) msk[buf * AT_BK + tid] = maskg[kb0 + tid];
    };
    loadKV(0, 0);       cp_commit();   // G0 (incl. Q)
    loadKV(AT_BK, 1);   cp_commit();   // G1

    float O[16][4];
    #pragma unroll
    for (int nt = 0; nt < 16; nt++)
        #pragma unroll
        for (int c = 0; c < 4; c++) O[nt][c] = 0.f;
    float m_lo = -1e30f, m_hi = -1e30f, l_lo = 0.f, l_hi = 0.f;

    const float scale = 0.08838834764831845f;   // 1/sqrt(128)
    const int nIter = S_ / AT_BK;               // 32

    const int aRow = (lane & 15);
    const int aChunk = (lane >> 4) << 4;
    const int li = lane >> 3;
    const int bRowOff = ((li >> 1) << 3) + (lane & 7);
    const int bChunk = (li & 1) << 4;
    const uint32_t qaddr0 = qbase + (w * 16 + aRow) * AQ_ROWB + aChunk;

    for (int kt = 0; kt < nIter; kt++) {
        cp_wait<1>();                  // buffer kt&1 loads complete
        __syncthreads();

        const int buf = kt & 1;
        const uint32_t kbs = kvbase + buf * 2 * AT_KVB;
        const uint32_t vbs = kbs + AT_KVB;
        const float* mk = msk + buf * AT_BK;

        // ---- S = Q @ K^T (16x64 per warp), 8 k16 steps ----
        float sacc[8][4] = {};
        #pragma unroll
        for (int k16 = 0; k16 < 8; k16++) {
            uint32_t af[4], bf[4][4];
            ldmx4(af, qaddr0 + k16 * 32);
            #pragma unroll
            for (int np = 0; np < 4; np++)
                ldmx4(bf[np], kbs + (np * 16 + bRowOff) * AQ_ROWB
                              + bChunk + k16 * 32);
            #pragma unroll
            for (int np = 0; np < 4; np++) {
                mma_f16(sacc[np * 2 + 0], af, bf[np][0], bf[np][1]);
                mma_f16(sacc[np * 2 + 1], af, bf[np][2], bf[np][3]);
            }
        }

        // ---- scale + mask ----
        #pragma unroll
        for (int ni = 0; ni < 8; ni++)
            #pragma unroll
            for (int c = 0; c < 4; c++) {
                const int col = ni * 8 + 2 * t4 + (c & 1);
                sacc[ni][c] = sacc[ni][c] * scale + mk[col];
            }

        // ---- in-warp softmax ----
        float rm_lo = -1e30f, rm_hi = -1e30f;
        #pragma unroll
        for (int ni = 0; ni < 8; ni++) {
            rm_lo = fmaxf(rm_lo, fmaxf(sacc[ni][0], sacc[ni][1]));
            rm_hi = fmaxf(rm_hi, fmaxf(sacc[ni][2], sacc[ni][3]));
        }
        rm_lo = fmaxf(rm_lo, __shfl_xor_sync(0xffffffffu, rm_lo, 1));
        rm_lo = fmaxf(rm_lo, __shfl_xor_sync(0xffffffffu, rm_lo, 2));
        rm_hi = fmaxf(rm_hi, __shfl_xor_sync(0xffffffffu, rm_hi, 1));
        rm_hi = fmaxf(rm_hi, __shfl_xor_sync(0xffffffffu, rm_hi, 2));

        const float mn_lo = fmaxf(m_lo, rm_lo);
        const float mn_hi = fmaxf(m_hi, rm_hi);
        const float al_lo = __expf(m_lo - mn_lo);
        const float al_hi = __expf(m_hi - mn_hi);
        m_lo = mn_lo;
        m_hi = mn_hi;

        float sum_lo = 0.f, sum_hi = 0.f;
        #pragma unroll
        for (int ni = 0; ni < 8; ni++) {
            sacc[ni][0] = __expf(sacc[ni][0] - mn_lo);
            sacc[ni][1] = __expf(sacc[ni][1] - mn_lo);
            sacc[ni][2] = __expf(sacc[ni][2] - mn_hi);
            sacc[ni][3] = __expf(sacc[ni][3] - mn_hi);
            sum_lo += sacc[ni][0] + sacc[ni][1];
            sum_hi += sacc[ni][2] + sacc[ni][3];
        }
        sum_lo += __shfl_xor_sync(0xffffffffu, sum_lo, 1);
        sum_lo += __shfl_xor_sync(0xffffffffu, sum_lo, 2);
        sum_hi += __shfl_xor_sync(0xffffffffu, sum_hi, 1);
        sum_hi += __shfl_xor_sync(0xffffffffu, sum_hi, 2);
        l_lo = l_lo * al_lo + sum_lo;
        l_hi = l_hi * al_hi + sum_hi;

        #pragma unroll
        for (int nt = 0; nt < 16; nt++) {
            O[nt][0] *= al_lo;  O[nt][1] *= al_lo;
            O[nt][2] *= al_hi;  O[nt][3] *= al_hi;
        }

        // ---- O += P @ V ----
        #pragma unroll
        for (int kb2 = 0; kb2 < 4; kb2++) {
            uint32_t af[4];
            af[0] = packh2(sacc[2 * kb2][0],     sacc[2 * kb2][1]);
            af[1] = packh2(sacc[2 * kb2][2],     sacc[2 * kb2][3]);
            af[2] = packh2(sacc[2 * kb2 + 1][0], sacc[2 * kb2 + 1][1]);
            af[3] = packh2(sacc[2 * kb2 + 1][2], sacc[2 * kb2 + 1][3]);
            #pragma unroll
            for (int t = 0; t < 8; t++) {
                uint32_t bf[4];
                ldmx4t(bf, vbs + (kb2 * 16 + aRow) * AQ_ROWB
                           + (2 * t) * 16 + aChunk);
                mma_f16(O[2 * t + 0], af, bf[0], bf[1]);
                mma_f16(O[2 * t + 1], af, bf[2], bf[3]);
            }
        }

        __syncthreads();               // all warps done with buf before refill
        const int nt2 = kt + 2;
        if (nt2 < nIter) loadKV(nt2 * AT_BK, buf);
        cp_commit();                   // unconditional (group accounting)
    }

    // ---- finalize: /l, fp16, write TILE-BLOCKED layout for out-proj ----
    const int h = bh & (NH_ - 1);
    const float inv_lo = 1.f / l_lo;
    const float inv_hi = 1.f / l_hi;
    const int q_lo = q0 + w * 16 + g;
    const int mlo = b * S_ + q_lo;               // global row in [MTOT]
    const int mBlkBase = (mlo >> 7) * 32;        // same block for lo & hi rows
    const int rlo = mlo & 127;
    #pragma unroll
    for (int nt = 0; nt < 16; nt++) {
        const int col = nt * 8 + 2 * t4;
        const int hcol = h * HD_ + col;
        const size_t base = ((size_t)(mBlkBase + (hcol >> 6))) * BLKH + (hcol & 63);
        *(uint32_t*)&ablk[base + rlo * ROWH] =
            packh2(O[nt][0] * inv_lo, O[nt][1] * inv_lo);
        *(uint32_t*)&ablk[base + (rlo + 8) * ROWH] =
            packh2(O[nt][2] * inv_hi, O[nt][3] * inv_hi);
    }
}

// ---------------------------------------------------------------------------
// Launch
// ---------------------------------------------------------------------------
extern "C" void kernel_launch(void* const* d_in, const int* in_sizes, int n_in,
                              void* d_out, int out_size)
{
    const float* x    = (const float*)d_in[0];
    const float* mask = (const float*)d_in[1];
    const float* Wq   = (const float*)d_in[2];
    const float* bq   = (const float*)d_in[3];
    const float* Wk   = (const float*)d_in[4];
    const float* bk   = (const float*)d_in[5];
    const float* Wv   = (const float*)d_in[6];
    const float* bv   = (const float*)d_in[7];
    const float* Wo   = (const float*)d_in[8];
    const float* bo   = (const float*)d_in[9];
    float* out = (float*)d_out;

    __half *q, *k, *v, *xblk, *wblk, *wblk_o, *ablk;
    cudaGetSymbolAddress((void**)&q,      g_q);
    cudaGetSymbolAddress((void**)&k,      g_k);
    cudaGetSymbolAddress((void**)&v,      g_v);
    cudaGetSymbolAddress((void**)&xblk,   g_xblk);
    cudaGetSymbolAddress((void**)&wblk,   g_wblk);
    cudaGetSymbolAddress((void**)&wblk_o, g_wblk_o);
    cudaGetSymbolAddress((void**)&ablk,   g_ablk);

    cudaFuncSetAttribute(gemm_tma<true>,
                         cudaFuncAttributeMaxDynamicSharedMemorySize, GT_SMEM);
    cudaFuncSetAttribute(gemm_tma<false>,
                         cudaFuncAttributeMaxDynamicSharedMemorySize, GT_SMEM);
    cudaFuncSetAttribute(attn_h,
                         cudaFuncAttributeMaxDynamicSharedMemorySize, AT_SMEM);

    // Prep: x -> blocked fp16; weights -> blocked fp16 directly (one launch)
    x_to_blk<<<4096, 256>>>(x, xblk);
    transpose_blk4<<<dim3(H_ / 32, H_ / 32, 4), dim3(32, 8)>>>(
        Wq, Wk, Wv, Wo, wblk, wblk_o);

    // Fused QKV projection (N = 3*2048), TMA-bulk fills
    gemm_tma<true><<<dim3(48, 32), 256, GT_SMEM>>>(
        xblk, wblk, bq, bk, bv, q, k, v, nullptr);

    attn_h<<<dim3(S_ / 128, B_ * NH_), 256, AT_SMEM>>>(q, k, v, mask, ablk);

    // Out projection (fp32 output), TMA-bulk fills
    gemm_tma<false><<<dim3(16, 32), 256, GT_SMEM>>>(
        ablk, wblk_o, bo, nullptr, nullptr,
        nullptr, nullptr, nullptr, out);
}

// round 17
// speedup vs baseline: 1.1447x; 1.0183x over previous
#include <cuda_runtime.h>
#include <cuda_fp16.h>
#include <math.h>
#include <stdint.h>

// Problem constants
#define B_   2
#define S_   2048
#define H_   2048
#define NH_  16
#define HD_  128
#define MTOT (B_ * S_)          // 4096 rows for projection GEMMs

// Blocked-stage geometry (one GEMM pipeline stage operand block)
#define ROWB   144              // bytes per row (16B pad -> conflict-free ldmatrix)
#define ROWH   72               // halves per row
#define BLKB   (128 * ROWB)     // 18432 B per operand block (128 rows x 64 halves)
#define BLKH   (128 * ROWH)     // 9216 halves

// ---------------------------------------------------------------------------
// Device scratch
// ---------------------------------------------------------------------------
__device__ __half g_q[(size_t)B_ * NH_ * S_ * HD_];
__device__ __half g_k[(size_t)B_ * NH_ * S_ * HD_];
__device__ __half g_v[(size_t)B_ * NH_ * S_ * HD_];
__device__ __half g_xblk[(size_t)32 * 32 * BLKH];        // x, tile-blocked
__device__ __half g_wblk[(size_t)48 * 32 * BLKH];        // Wq|Wk|Wv^T, blocked
__device__ __half g_wblk_o[(size_t)16 * 32 * BLKH];      // Wo^T, blocked
__device__ __half g_ablk[(size_t)32 * 32 * BLKH];        // attn out, blocked

// ---------------------------------------------------------------------------
// Helpers
// ---------------------------------------------------------------------------
__device__ __forceinline__ uint32_t smem_u32(const void* p) {
    return (uint32_t)__cvta_generic_to_shared(p);
}
__device__ __forceinline__ void cp16(void* s, const void* g) {
    asm volatile("cp.async.cg.shared.global [%0], [%1], 16;"
                 :: "r"(smem_u32(s)), "l"(g));
}
__device__ __forceinline__ void cp_commit() {
    asm volatile("cp.async.commit_group;");
}
template <int N>
__device__ __forceinline__ void cp_wait() {
    asm volatile("cp.async.wait_group %0;" :: "n"(N));
}

// TMA bulk copy global -> shared with mbarrier completion (sm_90 ISA)
__device__ __forceinline__ void tma_bulk(uint32_t dst, const void* src,
                                         uint32_t bytes, uint32_t mbar) {
    asm volatile(
        "cp.async.bulk.shared::cluster.global.mbarrier::complete_tx::bytes "
        "[%0], [%1], %2, [%3];"
        :: "r"(dst), "l"(src), "r"(bytes), "r"(mbar) : "memory");
}

#define MBAR_INIT(mbar, cnt) \
    asm volatile("mbarrier.init.shared.b64 [%0], %1;" :: "r"(mbar), "r"(cnt) : "memory")
#define MBAR_EXPECT_TX(mbar, bytes) \
    asm volatile("mbarrier.arrive.expect_tx.shared.b64 _, [%0], %1;" \
                 :: "r"(mbar), "r"(bytes) : "memory")
#define MBAR_WAIT(mbar, parity) do {                                        \
    uint32_t _m = (mbar), _p = (parity), _d;                                \
    asm volatile("{\n\t.reg .pred p;\n\t"                                   \
        "mbarrier.try_wait.parity.acquire.cta.shared::cta.b64 p, [%1], %2;\n\t" \
        "selp.b32 %0, 1, 0, p;\n\t}"                                        \
        : "=r"(_d) : "r"(_m), "r"(_p) : "memory");                          \
    if (!_d) {                                                              \
        asm volatile("{\n\t.reg .pred P1;\n\t"                              \
        "W_%=:\n\t"                                                         \
        "mbarrier.try_wait.parity.acquire.cta.shared::cta.b64 P1, [%0], %1, 0x989680;\n\t" \
        "@P1 bra.uni D_%=;\n\t"                                             \
        "bra.uni W_%=;\n\t"                                                 \
        "D_%=:\n\t}" :: "r"(_m), "r"(_p) : "memory");                       \
    }                                                                       \
} while (0)

__device__ __forceinline__ void ldmx4(uint32_t (&r)[4], uint32_t a) {
    asm volatile("ldmatrix.sync.aligned.m8n8.x4.shared.b16 {%0,%1,%2,%3}, [%4];"
                 : "=r"(r[0]), "=r"(r[1]), "=r"(r[2]), "=r"(r[3]) : "r"(a));
}
__device__ __forceinline__ void ldmx4t(uint32_t (&r)[4], uint32_t a) {
    asm volatile("ldmatrix.sync.aligned.m8n8.x4.trans.shared.b16 {%0,%1,%2,%3}, [%4];"
                 : "=r"(r[0]), "=r"(r[1]), "=r"(r[2]), "=r"(r[3]) : "r"(a));
}

// m16n8k16 fp16 mma, fp32 accumulate.
__device__ __forceinline__ void mma_f16(float (&c)[4], const uint32_t (&a)[4],
                                        uint32_t b0, uint32_t b1) {
    asm volatile(
        "mma.sync.aligned.m16n8k16.row.col.f32.f16.f16.f32 "
        "{%0,%1,%2,%3}, {%4,%5,%6,%7}, {%8,%9}, {%0,%1,%2,%3};\n"
        : "+f"(c[0]), "+f"(c[1]), "+f"(c[2]), "+f"(c[3])
        : "r"(a[0]), "r"(a[1]), "r"(a[2]), "r"(a[3]), "r"(b0), "r"(b1));
}

__device__ __forceinline__ uint32_t packh2(float lo, float hi) {
    __half2 h = __float22half2_rn(make_float2(lo, hi));
    return *reinterpret_cast<uint32_t*>(&h);
}
__device__ __forceinline__ float ex2f(float x) {
    float r;
    asm("ex2.approx.f32 %0, %1;" : "=f"(r) : "f"(x));
    return r;
}

#define LOG2E 1.4426950408889634f
#define QSC   (0.08838834764831845f * LOG2E)   // 1/sqrt(128) * log2(e)

// ---------------------------------------------------------------------------
// Prep kernels
// ---------------------------------------------------------------------------
// x (fp32 [M][K]) -> fp16 tile-blocked (blk = (m>>7)*32 + (k>>6))
__global__ void x_to_blk(const float* __restrict__ x, __half* __restrict__ dst)
{
    int id = blockIdx.x * 256 + threadIdx.x;     // 32*32*1024 ids
    int blk = id >> 10;
    int r = (id >> 3) & 127;
    int c = id & 7;
    int m = (blk >> 5) * 128 + r;
    int k = (blk & 31) * 64 + c * 8;
    const float4* s = (const float4*)(x + (size_t)m * H_ + k);
    float4 v0 = s[0], v1 = s[1];
    uint4 o;
    o.x = packh2(v0.x, v0.y); o.y = packh2(v0.z, v0.w);
    o.z = packh2(v1.x, v1.y); o.w = packh2(v1.z, v1.w);
    *(uint4*)(dst + (size_t)blk * BLKH + r * ROWH + c * 8) = o;
}

// Transpose + fp16 + tile-blocked directly (no flat intermediate)
__global__ void transpose_blk4(const float* __restrict__ W0,
                               const float* __restrict__ W1,
                               const float* __restrict__ W2,
                               const float* __restrict__ W3,
                               __half* __restrict__ wqkv,
                               __half* __restrict__ wo)
{
    const int z = blockIdx.z;
    const float* W = (z == 0) ? W0 : (z == 1) ? W1 : (z == 2) ? W2 : W3;

    __shared__ float t[32][33];
    int n0 = blockIdx.x * 32, k0 = blockIdx.y * 32;
    int tx = threadIdx.x, ty = threadIdx.y;
    #pragma unroll
    for (int i = 0; i < 4; i++)
        t[ty + i * 8][tx] = W[(size_t)(k0 + ty + i * 8) * H_ + n0 + tx];
    __syncthreads();
    __half* dst = (z < 3) ? wqkv : wo;
    const int nOff = (z < 3) ? z * H_ : 0;
    const int k = k0 + tx;
    #pragma unroll
    for (int i = 0; i < 4; i++) {
        const int nG = nOff + n0 + ty + i * 8;
        dst[((size_t)((nG >> 7) * 32 + (k >> 6))) * BLKH
            + (nG & 127) * ROWH + (k & 63)] = __float2half(t[tx][ty + i * 8]);
    }
}

// ---------------------------------------------------------------------------
// TMA-bulk fp16 GEMM (PROVEN): 128x128 CTA tile, warp tile 64x32, BK=64,
// 3-stage pipeline, single-thread bulk fills, 2 CTAs/SM.
// FUSED: epilogue scatters fp16 Q/K/V; Q is pre-scaled by QSC (scale*log2e).
// ---------------------------------------------------------------------------
#define GT_STGB (2 * BLKB)                 // 36864 B per stage (A + B)
#define GT_SMEM (3 * GT_STGB + 64)         // + mbarrier block

template <bool FUSED>
__global__ __launch_bounds__(256, 2)
void gemm_tma(const __half* __restrict__ Ablk, const __half* __restrict__ Bblk,
              const float* __restrict__ b0v, const float* __restrict__ b1v,
              const float* __restrict__ b2v,
              __half* __restrict__ o0, __half* __restrict__ o1,
              __half* __restrict__ o2, float* __restrict__ of)
{
    extern __shared__ char smc[];
    const uint32_t sbase = smem_u32(smc);
    const uint32_t mbase = sbase + 3 * GT_STGB;

    const int tid = threadIdx.x;
    const int w = tid >> 5, lane = tid & 31, g = lane >> 2, t4 = lane & 3;
    const int wr = w >> 2, wc = w & 3;
    const int mBlk = blockIdx.y;           // 128-row block of A
    const int nBlk = blockIdx.x;           // 128-row block of W^T

    if (tid == 0) {
        #pragma unroll
        for (int s = 0; s < 3; s++) MBAR_INIT(mbase + 8 * s, 1);
    }
    __syncthreads();

    const char* Ab8 = (const char*)Ablk;
    const char* Bb8 = (const char*)Bblk;
    auto issue = [&](int kt, int s) {
        if (tid == 0) {
            const uint32_t mb = mbase + 8 * s;
            MBAR_EXPECT_TX(mb, GT_STGB);
            tma_bulk(sbase + s * GT_STGB,
                     Ab8 + (size_t)(mBlk * 32 + kt) * BLKB, BLKB, mb);
            tma_bulk(sbase + s * GT_STGB + BLKB,
                     Bb8 + (size_t)(nBlk * 32 + kt) * BLKB, BLKB, mb);
        }
    };

    issue(0, 0);
    issue(1, 1);

    float acc[4][4][4] = {};
    const int aRow = wr * 64 + (lane & 15);
    const int aChunk = (lane >> 4) << 4;
    const int li = lane >> 3;
    const int bRowOff = ((li >> 1) << 3) + (lane & 7);
    const int bChunk = (li & 1) << 4;

    int ph[3] = {0, 0, 0};
    const int nIter = 32;                  // K=2048 / 64

    for (int kt = 0; kt < nIter; kt++) {
        const int s = kt % 3;
        MBAR_WAIT(mbase + 8 * s, ph[s]);
        ph[s] ^= 1;
        __syncthreads();                   // all warps done with stage (kt+2)%3

        if (kt + 2 < nIter) issue(kt + 2, (kt + 2) % 3);

        const uint32_t Ab = sbase + s * GT_STGB;
        const uint32_t Bb = Ab + BLKB;

        #pragma unroll
        for (int k16 = 0; k16 < 4; k16++) {
            uint32_t af[4][4], bf[2][4];
            #pragma unroll
            for (int mi = 0; mi < 4; mi++)
                ldmx4(af[mi], Ab + (aRow + mi * 16) * ROWB + aChunk + k16 * 32);
            #pragma unroll
            for (int np = 0; np < 2; np++)
                ldmx4(bf[np], Bb + (wc * 32 + np * 16 + bRowOff) * ROWB
                              + bChunk + k16 * 32);
            #pragma unroll
            for (int mi = 0; mi < 4; mi++)
                #pragma unroll
                for (int np = 0; np < 2; np++) {
                    mma_f16(acc[mi][np * 2 + 0], af[mi], bf[np][0], bf[np][1]);
                    mma_f16(acc[mi][np * 2 + 1], af[mi], bf[np][2], bf[np][3]);
                }
        }
    }

    const int mBase = mBlk * 128;
    const int nBase = nBlk * 128;
    #pragma unroll
    for (int mi = 0; mi < 4; mi++) {
        #pragma unroll
        for (int r2 = 0; r2 < 2; r2++) {
            const int m = mBase + wr * 64 + mi * 16 + g + r2 * 8;
            #pragma unroll
            for (int ni = 0; ni < 4; ni++) {
                const int n = nBase + wc * 32 + ni * 8 + 2 * t4;
                if (FUSED) {
                    const int which = n >> 11;        // 0=Q 1=K 2=V
                    const int n2 = n & (H_ - 1);
                    const float* bias = (which == 0) ? b0v : (which == 1) ? b1v : b2v;
                    __half* dst = (which == 0) ? o0 : (which == 1) ? o1 : o2;
                    const float qs = (which == 0) ? QSC : 1.f;   // pre-scale Q
                    const int b = m >> 11;
                    const int s = m & (S_ - 1);
                    const int h = n2 >> 7;
                    const int d = n2 & (HD_ - 1);
                    uint32_t pv = packh2((acc[mi][ni][r2 * 2 + 0] + bias[n2]) * qs,
                                         (acc[mi][ni][r2 * 2 + 1] + bias[n2 + 1]) * qs);
                    *(uint32_t*)&dst[(((size_t)(b * NH_ + h)) * S_ + s) * HD_ + d] = pv;
                } else {
                    float2 v;
                    v.x = acc[mi][ni][r2 * 2 + 0] + b0v[n];
                    v.y = acc[mi][ni][r2 * 2 + 1] + b0v[n + 1];
                    *(float2*)&of[(size_t)m * H_ + n] = v;
                }
            }
        }
    }
}

// ---------------------------------------------------------------------------
// fp16 flash attention, BKT=64, double-buffered K/V (proven mainloop).
// Q pre-scaled by scale*log2e; softmax in log2 domain (ex2.approx);
// full mask row resident in smem, pre-multiplied by log2e.
// ---------------------------------------------------------------------------
#define AT_BK   64
#define AQ_ROWB 272
#define AT_KVB  (AT_BK * AQ_ROWB)                          // 17408 B
#define AT_SMEM (128 * AQ_ROWB + 4 * AT_KVB + S_ * 4)      // 112640 B

__global__ __launch_bounds__(256, 2)
void attn_h(const __half* __restrict__ Q, const __half* __restrict__ K,
            const __half* __restrict__ V, const float* __restrict__ mask,
            __half* __restrict__ ablk)
{
    extern __shared__ char smc[];
    char* Qs = smc;                              // 128 x 272 B
    char* KV = Qs + 128 * AQ_ROWB;               // 2 x (K 64x272 + V 64x272)
    float* msk = (float*)(KV + 4 * AT_KVB);      // full row, 2048 f32 (log2e-scaled)
    const uint32_t qbase  = smem_u32(Qs);
    const uint32_t kvbase = smem_u32(KV);

    const int tid = threadIdx.x;
    const int w = tid >> 5, lane = tid & 31, g = lane >> 2, t4 = lane & 3;
    const int bh = blockIdx.y;
    const int b  = bh >> 4;
    const int q0 = blockIdx.x * 128;

    const __half* Qg = Q + ((size_t)bh * S_ + q0) * HD_;
    const __half* Kg = K + (size_t)bh * S_ * HD_;
    const __half* Vg = V + (size_t)bh * S_ * HD_;
    const float* maskg = mask + (size_t)b * S_;

    // mask row resident (plain loads; no cp.async group interaction)
    #pragma unroll
    for (int i = 0; i < 8; i++)
        msk[tid + i * 256] = maskg[tid + i * 256] * LOG2E;

    #pragma unroll
    for (int i = 0; i < 8; i++) {
        int id = tid + i * 256;
        int r = id >> 4, c = id & 15;
        cp16(Qs + r * AQ_ROWB + c * 16, Qg + (size_t)r * HD_ + c * 8);
    }
    auto loadKV = [&](int kb0, int buf) {
        char* Kb = KV + buf * 2 * AT_KVB;
        char* Vb = Kb + AT_KVB;
        #pragma unroll
        for (int i = 0; i < 4; i++) {
            int id = tid + i * 256;
            int r = id >> 4, c = id & 15;
            cp16(Kb + r * AQ_ROWB + c * 16, Kg + (size_t)(kb0 + r) * HD_ + c * 8);
            cp16(Vb + r * AQ_ROWB + c * 16, Vg + (size_t)(kb0 + r) * HD_ + c * 8);
        }
    };
    loadKV(0, 0);       cp_commit();   // G0 (incl. Q)
    loadKV(AT_BK, 1);   cp_commit();   // G1

    float O[16][4];
    #pragma unroll
    for (int nt = 0; nt < 16; nt++)
        #pragma unroll
        for (int c = 0; c < 4; c++) O[nt][c] = 0.f;
    float m_lo = -1e30f, m_hi = -1e30f, l_lo = 0.f, l_hi = 0.f;

    const int nIter = S_ / AT_BK;               // 32

    const int aRow = (lane & 15);
    const int aChunk = (lane >> 4) << 4;
    const int li = lane >> 3;
    const int bRowOff = ((li >> 1) << 3) + (lane & 7);
    const int bChunk = (li & 1) << 4;
    const uint32_t qaddr0 = qbase + (w * 16 + aRow) * AQ_ROWB + aChunk;

    for (int kt = 0; kt < nIter; kt++) {
        cp_wait<1>();                  // buffer kt&1 loads complete
        __syncthreads();

        const int buf = kt & 1;
        const uint32_t kbs = kvbase + buf * 2 * AT_KVB;
        const uint32_t vbs = kbs + AT_KVB;
        const float* mk = msk + kt * AT_BK;

        // ---- S' = (Q*scale*log2e) @ K^T (16x64 per warp), 8 k16 steps ----
        float sacc[8][4] = {};
        #pragma unroll
        for (int k16 = 0; k16 < 8; k16++) {
            uint32_t af[4], bf[4][4];
            ldmx4(af, qaddr0 + k16 * 32);
            #pragma unroll
            for (int np = 0; np < 4; np++)
                ldmx4(bf[np], kbs + (np * 16 + bRowOff) * AQ_ROWB
                              + bChunk + k16 * 32);
            #pragma unroll
            for (int np = 0; np < 4; np++) {
                mma_f16(sacc[np * 2 + 0], af, bf[np][0], bf[np][1]);
                mma_f16(sacc[np * 2 + 1], af, bf[np][2], bf[np][3]);
            }
        }

        // ---- add (log2e-scaled) mask ----
        #pragma unroll
        for (int ni = 0; ni < 8; ni++)
            #pragma unroll
            for (int c = 0; c < 4; c++) {
                const int col = ni * 8 + 2 * t4 + (c & 1);
                sacc[ni][c] = sacc[ni][c] + mk[col];
            }

        // ---- in-warp softmax (log2 domain, ex2) ----
        float rm_lo = -1e30f, rm_hi = -1e30f;
        #pragma unroll
        for (int ni = 0; ni < 8; ni++) {
            rm_lo = fmaxf(rm_lo, fmaxf(sacc[ni][0], sacc[ni][1]));
            rm_hi = fmaxf(rm_hi, fmaxf(sacc[ni][2], sacc[ni][3]));
        }
        rm_lo = fmaxf(rm_lo, __shfl_xor_sync(0xffffffffu, rm_lo, 1));
        rm_lo = fmaxf(rm_lo, __shfl_xor_sync(0xffffffffu, rm_lo, 2));
        rm_hi = fmaxf(rm_hi, __shfl_xor_sync(0xffffffffu, rm_hi, 1));
        rm_hi = fmaxf(rm_hi, __shfl_xor_sync(0xffffffffu, rm_hi, 2));

        const float mn_lo = fmaxf(m_lo, rm_lo);
        const float mn_hi = fmaxf(m_hi, rm_hi);
        const float al_lo = ex2f(m_lo - mn_lo);
        const float al_hi = ex2f(m_hi - mn_hi);
        m_lo = mn_lo;
        m_hi = mn_hi;

        float sum_lo = 0.f, sum_hi = 0.f;
        #pragma unroll
        for (int ni = 0; ni < 8; ni++) {
            sacc[ni][0] = ex2f(sacc[ni][0] - mn_lo);
            sacc[ni][1] = ex2f(sacc[ni][1] - mn_lo);
            sacc[ni][2] = ex2f(sacc[ni][2] - mn_hi);
            sacc[ni][3] = ex2f(sacc[ni][3] - mn_hi);
            sum_lo += sacc[ni][0] + sacc[ni][1];
            sum_hi += sacc[ni][2] + sacc[ni][3];
        }
        sum_lo += __shfl_xor_sync(0xffffffffu, sum_lo, 1);
        sum_lo += __shfl_xor_sync(0xffffffffu, sum_lo, 2);
        sum_hi += __shfl_xor_sync(0xffffffffu, sum_hi, 1);
        sum_hi += __shfl_xor_sync(0xffffffffu, sum_hi, 2);
        l_lo = l_lo * al_lo + sum_lo;
        l_hi = l_hi * al_hi + sum_hi;

        #pragma unroll
        for (int nt = 0; nt < 16; nt++) {
            O[nt][0] *= al_lo;  O[nt][1] *= al_lo;
            O[nt][2] *= al_hi;  O[nt][3] *= al_hi;
        }

        // ---- O += P @ V ----
        #pragma unroll
        for (int kb2 = 0; kb2 < 4; kb2++) {
            uint32_t af[4];
            af[0] = packh2(sacc[2 * kb2][0],     sacc[2 * kb2][1]);
            af[1] = packh2(sacc[2 * kb2][2],     sacc[2 * kb2][3]);
            af[2] = packh2(sacc[2 * kb2 + 1][0], sacc[2 * kb2 + 1][1]);
            af[3] = packh2(sacc[2 * kb2 + 1][2], sacc[2 * kb2 + 1][3]);
            #pragma unroll
            for (int t = 0; t < 8; t++) {
                uint32_t bf[4];
                ldmx4t(bf, vbs + (kb2 * 16 + aRow) * AQ_ROWB
                           + (2 * t) * 16 + aChunk);
                mma_f16(O[2 * t + 0], af, bf[0], bf[1]);
                mma_f16(O[2 * t + 1], af, bf[2], bf[3]);
            }
        }

        __syncthreads();               // all warps done with buf before refill
        const int nt2 = kt + 2;
        if (nt2 < nIter) loadKV(nt2 * AT_BK, buf);
        cp_commit();                   // unconditional (group accounting)
    }

    // ---- finalize: /l, fp16, write TILE-BLOCKED layout for out-proj ----
    const int h = bh & (NH_ - 1);
    const float inv_lo = 1.f / l_lo;
    const float inv_hi = 1.f / l_hi;
    const int q_lo = q0 + w * 16 + g;
    const int mlo = b * S_ + q_lo;               // global row in [MTOT]
    const int mBlkBase = (mlo >> 7) * 32;        // same block for lo & hi rows
    const int rlo = mlo & 127;
    #pragma unroll
    for (int nt = 0; nt < 16; nt++) {
        const int col = nt * 8 + 2 * t4;
        const int hcol = h * HD_ + col;
        const size_t base = ((size_t)(mBlkBase + (hcol >> 6))) * BLKH + (hcol & 63);
        *(uint32_t*)&ablk[base + rlo * ROWH] =
            packh2(O[nt][0] * inv_lo, O[nt][1] * inv_lo);
        *(uint32_t*)&ablk[base + (rlo + 8) * ROWH] =
            packh2(O[nt][2] * inv_hi, O[nt][3] * inv_hi);
    }
}

// ---------------------------------------------------------------------------
// Launch
// ---------------------------------------------------------------------------
extern "C" void kernel_launch(void* const* d_in, const int* in_sizes, int n_in,
                              void* d_out, int out_size)
{
    const float* x    = (const float*)d_in[0];
    const float* mask = (const float*)d_in[1];
    const float* Wq   = (const float*)d_in[2];
    const float* bq   = (const float*)d_in[3];
    const float* Wk   = (const float*)d_in[4];
    const float* bk   = (const float*)d_in[5];
    const float* Wv   = (const float*)d_in[6];
    const float* bv   = (const float*)d_in[7];
    const float* Wo   = (const float*)d_in[8];
    const float* bo   = (const float*)d_in[9];
    float* out = (float*)d_out;

    __half *q, *k, *v, *xblk, *wblk, *wblk_o, *ablk;
    cudaGetSymbolAddress((void**)&q,      g_q);
    cudaGetSymbolAddress((void**)&k,      g_k);
    cudaGetSymbolAddress((void**)&v,      g_v);
    cudaGetSymbolAddress((void**)&xblk,   g_xblk);
    cudaGetSymbolAddress((void**)&wblk,   g_wblk);
    cudaGetSymbolAddress((void**)&wblk_o, g_wblk_o);
    cudaGetSymbolAddress((void**)&ablk,   g_ablk);

    cudaFuncSetAttribute(gemm_tma<true>,
                         cudaFuncAttributeMaxDynamicSharedMemorySize, GT_SMEM);
    cudaFuncSetAttribute(gemm_tma<false>,
                         cudaFuncAttributeMaxDynamicSharedMemorySize, GT_SMEM);
    cudaFuncSetAttribute(attn_h,
                         cudaFuncAttributeMaxDynamicSharedMemorySize, AT_SMEM);

    // Prep: x -> blocked fp16; weights -> blocked fp16 directly (one launch)
    x_to_blk<<<4096, 256>>>(x, xblk);
    transpose_blk4<<<dim3(H_ / 32, H_ / 32, 4), dim3(32, 8)>>>(
        Wq, Wk, Wv, Wo, wblk, wblk_o);

    // Fused QKV projection (N = 3*2048), TMA-bulk fills
    gemm_tma<true><<<dim3(48, 32), 256, GT_SMEM>>>(
        xblk, wblk, bq, bk, bv, q, k, v, nullptr);

    attn_h<<<dim3(S_ / 128, B_ * NH_), 256, AT_SMEM>>>(q, k, v, mask, ablk);

    // Out projection (fp32 output), TMA-bulk fills
    gemm_tma<false><<<dim3(16, 32), 256, GT_SMEM>>>(
        ablk, wblk_o, bo, nullptr, nullptr,
        nullptr, nullptr, nullptr, out);
}